// round 1
// baseline (speedup 1.0000x reference)
#include <cuda_runtime.h>
#include <math.h>

#define TT 2048
#define DIMD 2048
#define NH 16
#define NKVH 4
#define HD 128
#define NQ (NH*HD)     // 2048
#define NKV (NKVH*HD)  // 512
#define REP (NH/NKVH)  // 4

// Scratch (device globals; allocation in kernel_launch is forbidden)
__device__ float g_q[TT*NQ];
__device__ float g_k[TT*NKV];
__device__ float g_v[TT*NKV];
__device__ float g_att[TT*NQ];

// ---------------------------------------------------------------------------
// C[M,N] = A[M,K] * B[N,K]^T, all row-major. BM=BN=128, BK=16, 256 thr, 8x8.
// ---------------------------------------------------------------------------
__global__ __launch_bounds__(256, 2) void gemm_nt_kernel(
    const float* __restrict__ A, const float* __restrict__ B,
    float* __restrict__ C, int M, int N, int K)
{
    const int BK = 16;
    __shared__ float As[BK][132];   // [k][m], padded
    __shared__ float Bs[BK][132];   // [k][n], padded

    int tid = threadIdx.x;
    int tx = tid & 15;       // 0..15
    int ty = tid >> 4;       // 0..15
    int bm = blockIdx.y * 128;
    int bn = blockIdx.x * 128;

    float acc[8][8];
#pragma unroll
    for (int i = 0; i < 8; i++)
#pragma unroll
        for (int j = 0; j < 8; j++) acc[i][j] = 0.f;

    for (int k0 = 0; k0 < K; k0 += BK) {
        // Load tiles: 128 rows x 16 cols each = 512 float4; 2 per thread each.
#pragma unroll
        for (int i = 0; i < 2; i++) {
            int idx = tid + 256 * i;        // 0..511
            int row = idx >> 2;             // 0..127
            int c4  = (idx & 3) * 4;        // 0,4,8,12
            float4 va = *(const float4*)&A[(size_t)(bm + row) * K + k0 + c4];
            As[c4+0][row] = va.x; As[c4+1][row] = va.y;
            As[c4+2][row] = va.z; As[c4+3][row] = va.w;
            float4 vb = *(const float4*)&B[(size_t)(bn + row) * K + k0 + c4];
            Bs[c4+0][row] = vb.x; Bs[c4+1][row] = vb.y;
            Bs[c4+2][row] = vb.z; Bs[c4+3][row] = vb.w;
        }
        __syncthreads();

#pragma unroll
        for (int k = 0; k < BK; k++) {
            float a[8], b[8];
            *(float4*)&a[0] = *(const float4*)&As[k][ty*8];
            *(float4*)&a[4] = *(const float4*)&As[k][ty*8+4];
            *(float4*)&b[0] = *(const float4*)&Bs[k][tx*8];
            *(float4*)&b[4] = *(const float4*)&Bs[k][tx*8+4];
#pragma unroll
            for (int i = 0; i < 8; i++)
#pragma unroll
                for (int j = 0; j < 8; j++)
                    acc[i][j] += a[i] * b[j];
        }
        __syncthreads();
    }

#pragma unroll
    for (int i = 0; i < 8; i++) {
        int row = bm + ty*8 + i;
#pragma unroll
        for (int j = 0; j < 8; j += 4) {
            float4 v = make_float4(acc[i][j], acc[i][j+1], acc[i][j+2], acc[i][j+3]);
            *(float4*)&C[(size_t)row * N + bn + tx*8 + j] = v;
        }
    }
}

// ---------------------------------------------------------------------------
// In-place RoPE on u[T, heads, HD]; also applies `scale` (1/sqrt(HD) for Q).
// cos/sin are [T, HD] with cos[t,i] == cos[t,i+64].
// ---------------------------------------------------------------------------
__global__ void rope_kernel(float* __restrict__ u,
                            const float* __restrict__ cs,
                            const float* __restrict__ sn,
                            int heads, float scale)
{
    int idx = blockIdx.x * blockDim.x + threadIdx.x;    // T*heads*64 threads
    int i = idx & 63;
    int h = (idx >> 6) % heads;
    int t = idx / (64 * heads);
    if (t >= TT) return;
    float c = cs[t * HD + i];
    float s = sn[t * HD + i];
    float* p = u + ((size_t)t * heads + h) * HD;
    float u1 = p[i], u2 = p[i + 64];
    p[i]      = (u1 * c - u2 * s) * scale;
    p[i + 64] = (u2 * c + u1 * s) * scale;
}

// ---------------------------------------------------------------------------
// Flash attention, fp32. Grid (T/64, NH). 256 threads. BM=BN=64, HD=128.
// Q pre-scaled by 1/sqrt(HD). Causal.
// Smem: Qs[64][132], Ks[64][132], Vs[64][128], Ss[64][66], stats 3*64.
// ---------------------------------------------------------------------------
#define FA_SMEM ((64*132 + 64*132 + 64*128 + 64*66 + 192) * 4)

__global__ __launch_bounds__(256, 1) void fa_kernel(float* __restrict__ att)
{
    extern __shared__ float sm[];
    float* Qs   = sm;                    // [64][132]
    float* Ks   = Qs + 64*132;           // [64][132]
    float* Vs   = Ks + 64*132;           // [64][128]
    float* Ss   = Vs + 64*128;           // [64][66]
    float* sm_m = Ss + 64*66;            // [64]
    float* sm_l = sm_m + 64;             // [64]
    float* sm_a = sm_l + 64;             // [64]

    int tid = threadIdx.x;
    int tx = tid & 15;
    int ty = tid >> 4;
    int qb = blockIdx.x;          // query block, 0..31
    int h  = blockIdx.y;          // q head
    int g  = h / REP;             // kv head

    // Load Q tile: 64 rows x 128 cols = 2048 float4; 8/thread.
#pragma unroll
    for (int i = 0; i < 8; i++) {
        int idx = tid + 256 * i;
        int r = idx >> 5;
        int c4 = (idx & 31) * 4;
        float4 v = *(const float4*)&g_q[(size_t)(qb*64 + r) * NQ + h*HD + c4];
        *(float4*)&Qs[r*132 + c4] = v;
    }
    if (tid < 64) { sm_m[tid] = -1e30f; sm_l[tid] = 0.f; }

    float o[4][8];
#pragma unroll
    for (int i = 0; i < 4; i++)
#pragma unroll
        for (int j = 0; j < 8; j++) o[i][j] = 0.f;

    __syncthreads();

    for (int kb = 0; kb <= qb; kb++) {
        // Load K, V tiles
#pragma unroll
        for (int i = 0; i < 8; i++) {
            int idx = tid + 256 * i;
            int r = idx >> 5;
            int c4 = (idx & 31) * 4;
            *(float4*)&Ks[r*132 + c4] =
                *(const float4*)&g_k[(size_t)(kb*64 + r) * NKV + g*HD + c4];
            *(float4*)&Vs[r*128 + c4] =
                *(const float4*)&g_v[(size_t)(kb*64 + r) * NKV + g*HD + c4];
        }
        __syncthreads();

        // S = Q K^T  (64x64, inner 128). Each thread: 4x4 tile.
        float s[4][4];
#pragma unroll
        for (int i = 0; i < 4; i++)
#pragma unroll
            for (int j = 0; j < 4; j++) s[i][j] = 0.f;

#pragma unroll 4
        for (int k = 0; k < HD; k += 4) {
            float4 qv[4], kv[4];
#pragma unroll
            for (int i = 0; i < 4; i++)
                qv[i] = *(const float4*)&Qs[(ty + 16*i)*132 + k];
#pragma unroll
            for (int j = 0; j < 4; j++)
                kv[j] = *(const float4*)&Ks[(tx + 16*j)*132 + k];
#pragma unroll
            for (int i = 0; i < 4; i++)
#pragma unroll
                for (int j = 0; j < 4; j++)
                    s[i][j] += qv[i].x*kv[j].x + qv[i].y*kv[j].y
                             + qv[i].z*kv[j].z + qv[i].w*kv[j].w;
        }

        // Causal mask + store to smem
        int rg0 = qb * 64, cg0 = kb * 64;
#pragma unroll
        for (int i = 0; i < 4; i++) {
            int r = ty + 16*i;
#pragma unroll
            for (int j = 0; j < 4; j++) {
                int c = tx + 16*j;
                float val = s[i][j];
                if (cg0 + c > rg0 + r) val = -1e30f;
                Ss[r*66 + c] = val;
            }
        }
        __syncthreads();

        // Online softmax row stats (one thread per row)
        if (tid < 64) {
            float mold = sm_m[tid];
            float mx = mold;
            float* srow = &Ss[tid*66];
#pragma unroll 8
            for (int c = 0; c < 64; c++) mx = fmaxf(mx, srow[c]);
            float alpha = __expf(mold - mx);
            float l = sm_l[tid] * alpha;
#pragma unroll 8
            for (int c = 0; c < 64; c++) {
                float p = __expf(srow[c] - mx);
                srow[c] = p;
                l += p;
            }
            sm_m[tid] = mx; sm_l[tid] = l; sm_a[tid] = alpha;
        }
        __syncthreads();

        // Rescale accumulators, then O += P @ V
#pragma unroll
        for (int i = 0; i < 4; i++) {
            float a = sm_a[ty + 16*i];
#pragma unroll
            for (int j = 0; j < 8; j++) o[i][j] *= a;
        }
#pragma unroll 2
        for (int c = 0; c < 64; c++) {
            float p[4];
#pragma unroll
            for (int i = 0; i < 4; i++) p[i] = Ss[(ty + 16*i)*66 + c];
            float4 v0 = *(const float4*)&Vs[c*128 + tx*8];
            float4 v1 = *(const float4*)&Vs[c*128 + tx*8 + 4];
#pragma unroll
            for (int i = 0; i < 4; i++) {
                o[i][0] += p[i]*v0.x; o[i][1] += p[i]*v0.y;
                o[i][2] += p[i]*v0.z; o[i][3] += p[i]*v0.w;
                o[i][4] += p[i]*v1.x; o[i][5] += p[i]*v1.y;
                o[i][6] += p[i]*v1.z; o[i][7] += p[i]*v1.w;
            }
        }
        __syncthreads();
    }

    // Normalize and write out
#pragma unroll
    for (int i = 0; i < 4; i++) {
        int r = ty + 16*i;
        float inv = 1.0f / sm_l[r];
        size_t base = (size_t)(qb*64 + r) * NQ + h*HD + tx*8;
        float4 w0 = make_float4(o[i][0]*inv, o[i][1]*inv, o[i][2]*inv, o[i][3]*inv);
        float4 w1 = make_float4(o[i][4]*inv, o[i][5]*inv, o[i][6]*inv, o[i][7]*inv);
        *(float4*)&att[base]     = w0;
        *(float4*)&att[base + 4] = w1;
    }
}

// ---------------------------------------------------------------------------
extern "C" void kernel_launch(void* const* d_in, const int* in_sizes, int n_in,
                              void* d_out, int out_size)
{
    const float* x  = (const float*)d_in[0];
    const float* wq = (const float*)d_in[1];
    const float* wk = (const float*)d_in[2];
    const float* wv = (const float*)d_in[3];
    const float* wo = (const float*)d_in[4];
    const float* cs = (const float*)d_in[5];
    const float* sn = (const float*)d_in[6];
    float* out = (float*)d_out;

    float *q, *k, *v, *att;
    cudaGetSymbolAddress((void**)&q,   g_q);
    cudaGetSymbolAddress((void**)&k,   g_k);
    cudaGetSymbolAddress((void**)&v,   g_v);
    cudaGetSymbolAddress((void**)&att, g_att);

    // QKV projections: C = x @ W^T
    gemm_nt_kernel<<<dim3(NQ/128,  TT/128), 256>>>(x, wq, q, TT, NQ,  DIMD);
    gemm_nt_kernel<<<dim3(NKV/128, TT/128), 256>>>(x, wk, k, TT, NKV, DIMD);
    gemm_nt_kernel<<<dim3(NKV/128, TT/128), 256>>>(x, wv, v, TT, NKV, DIMD);

    // RoPE (Q also gets the 1/sqrt(HD) softmax scale folded in)
    const float scale = 0.08838834764831845f;  // 128^-0.5
    rope_kernel<<<(TT*NH*64)/256,   256>>>(q, cs, sn, NH,   scale);
    rope_kernel<<<(TT*NKVH*64)/256, 256>>>(k, cs, sn, NKVH, 1.0f);

    // Flash attention
    cudaFuncSetAttribute(fa_kernel, cudaFuncAttributeMaxDynamicSharedMemorySize,
                         FA_SMEM);
    fa_kernel<<<dim3(TT/64, NH), 256, FA_SMEM>>>(att);

    // Output projection: out = att @ wo^T
    gemm_nt_kernel<<<dim3(DIMD/128, TT/128), 256>>>(att, wo, out, TT, DIMD, NQ);
}

// round 2
// speedup vs baseline: 1.8530x; 1.8530x over previous
#include <cuda_runtime.h>
#include <math.h>

#define TT 2048
#define DIMD 2048
#define NH 16
#define NKVH 4
#define HD 128
#define NQ (NH*HD)     // 2048
#define NKV (NKVH*HD)  // 512
#define REP (NH/NKVH)  // 4

// Scratch (device globals; allocation in kernel_launch is forbidden)
__device__ float g_q[TT*NQ];
__device__ float g_k[TT*NKV];
__device__ float g_v[TT*NKV];
__device__ float g_att[TT*NQ];
// tf32-rounded copies of GEMM inputs
__device__ float g_xr [TT*DIMD];
__device__ float g_wqr[NQ*DIMD];
__device__ float g_wkr[NKV*DIMD];
__device__ float g_wvr[NKV*DIMD];
__device__ float g_wor[DIMD*NQ];

// ---------------------------------------------------------------------------
// helpers
// ---------------------------------------------------------------------------
__device__ __forceinline__ unsigned f2tf(float f) {
    unsigned u; asm("cvt.rna.tf32.f32 %0, %1;" : "=r"(u) : "f"(f)); return u;
}

__global__ void round_tf32_kernel(const float* __restrict__ in,
                                  float* __restrict__ out, int n4)
{
    int i = blockIdx.x * blockDim.x + threadIdx.x;
    if (i >= n4) return;
    float4 v = ((const float4*)in)[i];
    uint4 o;
    o.x = f2tf(v.x); o.y = f2tf(v.y); o.z = f2tf(v.z); o.w = f2tf(v.w);
    ((uint4*)out)[i] = o;
}

__device__ __forceinline__ void cp_async16(unsigned saddr, const void* g) {
    asm volatile("cp.async.cg.shared.global [%0], [%1], 16;\n"
                 :: "r"(saddr), "l"(g));
}
__device__ __forceinline__ void cp_commit() {
    asm volatile("cp.async.commit_group;\n");
}
__device__ __forceinline__ void cp_wait0() {
    asm volatile("cp.async.wait_group 0;\n");
}
__device__ __forceinline__ void cp_wait1() {
    asm volatile("cp.async.wait_group 1;\n");
}

__device__ __forceinline__ void mma_tf32(float c[4], const unsigned a[4],
                                         const unsigned b[2]) {
    asm volatile(
        "mma.sync.aligned.m16n8k8.row.col.f32.tf32.tf32.f32 "
        "{%0,%1,%2,%3}, {%4,%5,%6,%7}, {%8,%9}, {%0,%1,%2,%3};\n"
        : "+f"(c[0]), "+f"(c[1]), "+f"(c[2]), "+f"(c[3])
        : "r"(a[0]), "r"(a[1]), "r"(a[2]), "r"(a[3]), "r"(b[0]), "r"(b[1]));
}

// ---------------------------------------------------------------------------
// Tensor-core tf32 GEMM: C[M,N] = A[M,K] * B[N,K]^T, A/B pre-rounded to tf32.
// 128x128 tile, BK=32, 256 threads (8 warps, 4x2), warp tile 32x64.
// Double-buffered cp.async pipeline. Dynamic smem: 2*2*128*36*4 = 73728 B.
// ---------------------------------------------------------------------------
#define BM 128
#define BN 128
#define BKK 32
#define SAST 36                  // smem row stride (floats): (4g+t) conflict-free
#define GEMM_ASZ (BM*SAST)       // 4608 floats per operand tile
#define GEMM_STAGE (2*GEMM_ASZ)  // A + B
#define GEMM_SMEM (2*GEMM_STAGE*4)

__device__ __forceinline__ void gemm_tc(
    const float* __restrict__ A, const float* __restrict__ B,
    float* __restrict__ C, int M, int N, int K, int bm, int bn)
{
    extern __shared__ float smf[];
    int tid = threadIdx.x;
    int lane = tid & 31, wid = tid >> 5;
    int wm = (wid & 3) * 32;       // warp M offset
    int wn = (wid >> 2) * 64;      // warp N offset
    int g = lane >> 2, t = lane & 3;

    unsigned smem_base = (unsigned)__cvta_generic_to_shared(smf);

    float c[2][8][4];
#pragma unroll
    for (int mi = 0; mi < 2; mi++)
#pragma unroll
        for (int nj = 0; nj < 8; nj++)
#pragma unroll
            for (int r = 0; r < 4; r++) c[mi][nj][r] = 0.f;

    const int KT = K / BKK;

    auto load_stage = [&](int s, int kt) {
        int k0 = kt * BKK;
        unsigned sa = smem_base + (unsigned)(s * GEMM_STAGE) * 4u;
        unsigned sb = sa + (unsigned)GEMM_ASZ * 4u;
#pragma unroll
        for (int i = 0; i < 4; i++) {
            int idx = tid + 256 * i;     // 0..1023
            int row = idx >> 3;          // 0..127
            int kc  = (idx & 7) * 4;     // 0..28
            cp_async16(sa + (unsigned)(row * SAST + kc) * 4u,
                       &A[(size_t)(bm + row) * K + k0 + kc]);
            cp_async16(sb + (unsigned)(row * SAST + kc) * 4u,
                       &B[(size_t)(bn + row) * K + k0 + kc]);
        }
        cp_commit();
    };

    load_stage(0, 0);

    for (int kt = 0; kt < KT; kt++) {
        if (kt + 1 < KT) { load_stage((kt + 1) & 1, kt + 1); cp_wait1(); }
        else             { cp_wait0(); }
        __syncthreads();

        const float* As = smf + (kt & 1) * GEMM_STAGE;
        const float* Bs = As + GEMM_ASZ;

#pragma unroll
        for (int ks = 0; ks < 4; ks++) {
            int k0 = ks * 8;
            unsigned a[2][4], b[8][2];
#pragma unroll
            for (int mi = 0; mi < 2; mi++) {
                int r = wm + mi * 16;
                a[mi][0] = __float_as_uint(As[(r + g    ) * SAST + k0 + t    ]);
                a[mi][1] = __float_as_uint(As[(r + g + 8) * SAST + k0 + t    ]);
                a[mi][2] = __float_as_uint(As[(r + g    ) * SAST + k0 + t + 4]);
                a[mi][3] = __float_as_uint(As[(r + g + 8) * SAST + k0 + t + 4]);
            }
#pragma unroll
            for (int nj = 0; nj < 8; nj++) {
                int cb = wn + nj * 8;
                b[nj][0] = __float_as_uint(Bs[(cb + g) * SAST + k0 + t    ]);
                b[nj][1] = __float_as_uint(Bs[(cb + g) * SAST + k0 + t + 4]);
            }
#pragma unroll
            for (int mi = 0; mi < 2; mi++)
#pragma unroll
                for (int nj = 0; nj < 8; nj++)
                    mma_tf32(c[mi][nj], a[mi], b[nj]);
        }
        __syncthreads();
    }

    // epilogue
#pragma unroll
    for (int mi = 0; mi < 2; mi++) {
#pragma unroll
        for (int nj = 0; nj < 8; nj++) {
            int row0 = bm + wm + mi * 16 + g;
            int col  = bn + wn + nj * 8 + 2 * t;
            *(float2*)&C[(size_t)row0 * N + col] =
                make_float2(c[mi][nj][0], c[mi][nj][1]);
            *(float2*)&C[(size_t)(row0 + 8) * N + col] =
                make_float2(c[mi][nj][2], c[mi][nj][3]);
        }
    }
}

__global__ __launch_bounds__(256, 2) void gemm_tc_kernel(
    const float* __restrict__ A, const float* __restrict__ B,
    float* __restrict__ C, int M, int N, int K)
{
    gemm_tc(A, B, C, M, N, K, blockIdx.y * BM, blockIdx.x * BN);
}

__global__ __launch_bounds__(256, 2) void gemm_tc_kv_kernel(
    const float* __restrict__ A,
    const float* __restrict__ B0, const float* __restrict__ B1,
    float* __restrict__ C0, float* __restrict__ C1, int M, int N, int K)
{
    const float* B = blockIdx.z ? B1 : B0;
    float* C = blockIdx.z ? C1 : C0;
    gemm_tc(A, B, C, M, N, K, blockIdx.y * BM, blockIdx.x * BN);
}

// ---------------------------------------------------------------------------
// In-place RoPE on u[T, heads, HD]; also applies `scale` (1/sqrt(HD) for Q).
// ---------------------------------------------------------------------------
__global__ void rope_kernel(float* __restrict__ u,
                            const float* __restrict__ cs,
                            const float* __restrict__ sn,
                            int heads, float scale)
{
    int idx = blockIdx.x * blockDim.x + threadIdx.x;
    int i = idx & 63;
    int h = (idx >> 6) % heads;
    int t = idx / (64 * heads);
    if (t >= TT) return;
    float c = cs[t * HD + i];
    float s = sn[t * HD + i];
    float* p = u + ((size_t)t * heads + h) * HD;
    float u1 = p[i], u2 = p[i + 64];
    p[i]      = (u1 * c - u2 * s) * scale;
    p[i + 64] = (u2 * c + u1 * s) * scale;
}

// ---------------------------------------------------------------------------
// Flash attention, fp32 (unchanged); epilogue rounds output to tf32 so the
// out-projection's tensor-core GEMM consumes correctly-rounded inputs.
// ---------------------------------------------------------------------------
#define FA_SMEM ((64*132 + 64*132 + 64*128 + 64*66 + 192) * 4)

__global__ __launch_bounds__(256, 1) void fa_kernel(float* __restrict__ att)
{
    extern __shared__ float sm[];
    float* Qs   = sm;
    float* Ks   = Qs + 64*132;
    float* Vs   = Ks + 64*132;
    float* Ss   = Vs + 64*128;
    float* sm_m = Ss + 64*66;
    float* sm_l = sm_m + 64;
    float* sm_a = sm_l + 64;

    int tid = threadIdx.x;
    int tx = tid & 15;
    int ty = tid >> 4;
    int qb = blockIdx.x;
    int h  = blockIdx.y;
    int g  = h / REP;

#pragma unroll
    for (int i = 0; i < 8; i++) {
        int idx = tid + 256 * i;
        int r = idx >> 5;
        int c4 = (idx & 31) * 4;
        float4 v = *(const float4*)&g_q[(size_t)(qb*64 + r) * NQ + h*HD + c4];
        *(float4*)&Qs[r*132 + c4] = v;
    }
    if (tid < 64) { sm_m[tid] = -1e30f; sm_l[tid] = 0.f; }

    float o[4][8];
#pragma unroll
    for (int i = 0; i < 4; i++)
#pragma unroll
        for (int j = 0; j < 8; j++) o[i][j] = 0.f;

    __syncthreads();

    for (int kb = 0; kb <= qb; kb++) {
#pragma unroll
        for (int i = 0; i < 8; i++) {
            int idx = tid + 256 * i;
            int r = idx >> 5;
            int c4 = (idx & 31) * 4;
            *(float4*)&Ks[r*132 + c4] =
                *(const float4*)&g_k[(size_t)(kb*64 + r) * NKV + g*HD + c4];
            *(float4*)&Vs[r*128 + c4] =
                *(const float4*)&g_v[(size_t)(kb*64 + r) * NKV + g*HD + c4];
        }
        __syncthreads();

        float s[4][4];
#pragma unroll
        for (int i = 0; i < 4; i++)
#pragma unroll
            for (int j = 0; j < 4; j++) s[i][j] = 0.f;

#pragma unroll 4
        for (int k = 0; k < HD; k += 4) {
            float4 qv[4], kv[4];
#pragma unroll
            for (int i = 0; i < 4; i++)
                qv[i] = *(const float4*)&Qs[(ty + 16*i)*132 + k];
#pragma unroll
            for (int j = 0; j < 4; j++)
                kv[j] = *(const float4*)&Ks[(tx + 16*j)*132 + k];
#pragma unroll
            for (int i = 0; i < 4; i++)
#pragma unroll
                for (int j = 0; j < 4; j++)
                    s[i][j] += qv[i].x*kv[j].x + qv[i].y*kv[j].y
                             + qv[i].z*kv[j].z + qv[i].w*kv[j].w;
        }

        int rg0 = qb * 64, cg0 = kb * 64;
#pragma unroll
        for (int i = 0; i < 4; i++) {
            int r = ty + 16*i;
#pragma unroll
            for (int j = 0; j < 4; j++) {
                int c = tx + 16*j;
                float val = s[i][j];
                if (cg0 + c > rg0 + r) val = -1e30f;
                Ss[r*66 + c] = val;
            }
        }
        __syncthreads();

        if (tid < 64) {
            float mold = sm_m[tid];
            float mx = mold;
            float* srow = &Ss[tid*66];
#pragma unroll 8
            for (int c = 0; c < 64; c++) mx = fmaxf(mx, srow[c]);
            float alpha = __expf(mold - mx);
            float l = sm_l[tid] * alpha;
#pragma unroll 8
            for (int c = 0; c < 64; c++) {
                float p = __expf(srow[c] - mx);
                srow[c] = p;
                l += p;
            }
            sm_m[tid] = mx; sm_l[tid] = l; sm_a[tid] = alpha;
        }
        __syncthreads();

#pragma unroll
        for (int i = 0; i < 4; i++) {
            float a = sm_a[ty + 16*i];
#pragma unroll
            for (int j = 0; j < 8; j++) o[i][j] *= a;
        }
#pragma unroll 2
        for (int c = 0; c < 64; c++) {
            float p[4];
#pragma unroll
            for (int i = 0; i < 4; i++) p[i] = Ss[(ty + 16*i)*66 + c];
            float4 v0 = *(const float4*)&Vs[c*128 + tx*8];
            float4 v1 = *(const float4*)&Vs[c*128 + tx*8 + 4];
#pragma unroll
            for (int i = 0; i < 4; i++) {
                o[i][0] += p[i]*v0.x; o[i][1] += p[i]*v0.y;
                o[i][2] += p[i]*v0.z; o[i][3] += p[i]*v0.w;
                o[i][4] += p[i]*v1.x; o[i][5] += p[i]*v1.y;
                o[i][6] += p[i]*v1.z; o[i][7] += p[i]*v1.w;
            }
        }
        __syncthreads();
    }

#pragma unroll
    for (int i = 0; i < 4; i++) {
        int r = ty + 16*i;
        float inv = 1.0f / sm_l[r];
        size_t base = (size_t)(qb*64 + r) * NQ + h*HD + tx*8;
        uint4 w0, w1;
        w0.x = f2tf(o[i][0]*inv); w0.y = f2tf(o[i][1]*inv);
        w0.z = f2tf(o[i][2]*inv); w0.w = f2tf(o[i][3]*inv);
        w1.x = f2tf(o[i][4]*inv); w1.y = f2tf(o[i][5]*inv);
        w1.z = f2tf(o[i][6]*inv); w1.w = f2tf(o[i][7]*inv);
        *(uint4*)&att[base]     = w0;
        *(uint4*)&att[base + 4] = w1;
    }
}

// ---------------------------------------------------------------------------
extern "C" void kernel_launch(void* const* d_in, const int* in_sizes, int n_in,
                              void* d_out, int out_size)
{
    const float* x  = (const float*)d_in[0];
    const float* wq = (const float*)d_in[1];
    const float* wk = (const float*)d_in[2];
    const float* wv = (const float*)d_in[3];
    const float* wo = (const float*)d_in[4];
    const float* cs = (const float*)d_in[5];
    const float* sn = (const float*)d_in[6];
    float* out = (float*)d_out;

    float *q, *k, *v, *att, *xr, *wqr, *wkr, *wvr, *wor;
    cudaGetSymbolAddress((void**)&q,   g_q);
    cudaGetSymbolAddress((void**)&k,   g_k);
    cudaGetSymbolAddress((void**)&v,   g_v);
    cudaGetSymbolAddress((void**)&att, g_att);
    cudaGetSymbolAddress((void**)&xr,  g_xr);
    cudaGetSymbolAddress((void**)&wqr, g_wqr);
    cudaGetSymbolAddress((void**)&wkr, g_wkr);
    cudaGetSymbolAddress((void**)&wvr, g_wvr);
    cudaGetSymbolAddress((void**)&wor, g_wor);

    static bool attr_set = false;
    if (!attr_set) {
        cudaFuncSetAttribute(gemm_tc_kernel,
            cudaFuncAttributeMaxDynamicSharedMemorySize, GEMM_SMEM);
        cudaFuncSetAttribute(gemm_tc_kv_kernel,
            cudaFuncAttributeMaxDynamicSharedMemorySize, GEMM_SMEM);
        cudaFuncSetAttribute(fa_kernel,
            cudaFuncAttributeMaxDynamicSharedMemorySize, FA_SMEM);
        attr_set = true;
    }

    // Pre-round GEMM inputs to tf32 (one pass, memory-bound)
    round_tf32_kernel<<<(TT*DIMD/4 + 255)/256,  256>>>(x,  xr,  TT*DIMD/4);
    round_tf32_kernel<<<(NQ*DIMD/4 + 255)/256,  256>>>(wq, wqr, NQ*DIMD/4);
    round_tf32_kernel<<<(NKV*DIMD/4 + 255)/256, 256>>>(wk, wkr, NKV*DIMD/4);
    round_tf32_kernel<<<(NKV*DIMD/4 + 255)/256, 256>>>(wv, wvr, NKV*DIMD/4);
    round_tf32_kernel<<<(DIMD*NQ/4 + 255)/256,  256>>>(wo, wor, DIMD*NQ/4);

    // QKV projections on tensor cores
    gemm_tc_kernel<<<dim3(NQ/BN, TT/BM), 256, GEMM_SMEM>>>(
        xr, wqr, q, TT, NQ, DIMD);
    gemm_tc_kv_kernel<<<dim3(NKV/BN, TT/BM, 2), 256, GEMM_SMEM>>>(
        xr, wkr, wvr, k, v, TT, NKV, DIMD);

    // RoPE (Q also gets the 1/sqrt(HD) softmax scale folded in)
    const float scale = 0.08838834764831845f;  // 128^-0.5
    rope_kernel<<<(TT*NH*64)/256,   256>>>(q, cs, sn, NH,   scale);
    rope_kernel<<<(TT*NKVH*64)/256, 256>>>(k, cs, sn, NKVH, 1.0f);

    // Flash attention (fp32)
    fa_kernel<<<dim3(TT/64, NH), 256, FA_SMEM>>>(att);

    // Output projection on tensor cores
    gemm_tc_kernel<<<dim3(DIMD/BN, TT/BM), 256, GEMM_SMEM>>>(
        att, wor, out, TT, DIMD, NQ);
}

// round 3
// speedup vs baseline: 3.9878x; 2.1521x over previous
#include <cuda_runtime.h>
#include <math.h>

#define TT 2048
#define DIMD 2048
#define NH 16
#define NKVH 4
#define HD 128
#define NQ (NH*HD)     // 2048
#define NKV (NKVH*HD)  // 512
#define REP (NH/NKVH)  // 4

// Scratch (device globals; allocation in kernel_launch is forbidden)
__device__ float g_q[TT*NQ];
__device__ float g_k[TT*NKV];
__device__ float g_v[TT*NKV];
__device__ float g_att[TT*NQ];
// tf32-rounded copies of GEMM inputs
__device__ float g_xr [TT*DIMD];
__device__ float g_wqr[NQ*DIMD];
__device__ float g_wkr[NKV*DIMD];
__device__ float g_wvr[NKV*DIMD];
__device__ float g_wor[DIMD*NQ];

// ---------------------------------------------------------------------------
// helpers
// ---------------------------------------------------------------------------
__device__ __forceinline__ unsigned f2tf(float f) {
    unsigned u; asm("cvt.rna.tf32.f32 %0, %1;" : "=r"(u) : "f"(f)); return u;
}

__global__ void round_tf32_kernel(const float* __restrict__ in,
                                  float* __restrict__ out, int n4)
{
    int i = blockIdx.x * blockDim.x + threadIdx.x;
    if (i >= n4) return;
    float4 v = ((const float4*)in)[i];
    uint4 o;
    o.x = f2tf(v.x); o.y = f2tf(v.y); o.z = f2tf(v.z); o.w = f2tf(v.w);
    ((uint4*)out)[i] = o;
}

__device__ __forceinline__ void cp_async16(unsigned saddr, const void* g) {
    asm volatile("cp.async.cg.shared.global [%0], [%1], 16;\n"
                 :: "r"(saddr), "l"(g));
}
__device__ __forceinline__ void cp_commit() {
    asm volatile("cp.async.commit_group;\n");
}
__device__ __forceinline__ void cp_wait0() {
    asm volatile("cp.async.wait_group 0;\n");
}
__device__ __forceinline__ void cp_wait1() {
    asm volatile("cp.async.wait_group 1;\n");
}

__device__ __forceinline__ void mma_tf32(float c[4], const unsigned a[4],
                                         const unsigned b[2]) {
    asm volatile(
        "mma.sync.aligned.m16n8k8.row.col.f32.tf32.tf32.f32 "
        "{%0,%1,%2,%3}, {%4,%5,%6,%7}, {%8,%9}, {%0,%1,%2,%3};\n"
        : "+f"(c[0]), "+f"(c[1]), "+f"(c[2]), "+f"(c[3])
        : "r"(a[0]), "r"(a[1]), "r"(a[2]), "r"(a[3]), "r"(b[0]), "r"(b[1]));
}

// ---------------------------------------------------------------------------
// Tensor-core tf32 GEMM: C[M,N] = A[M,K] * B[N,K]^T, A/B pre-rounded to tf32.
// 128x128 tile, BK=32, 256 threads (8 warps, 4x2), warp tile 32x64.
// ---------------------------------------------------------------------------
#define BM 128
#define BN 128
#define BKK 32
#define SAST 36
#define GEMM_ASZ (BM*SAST)
#define GEMM_STAGE (2*GEMM_ASZ)
#define GEMM_SMEM (2*GEMM_STAGE*4)

__device__ __forceinline__ void gemm_tc(
    const float* __restrict__ A, const float* __restrict__ B,
    float* __restrict__ C, int M, int N, int K, int bm, int bn, int round_out)
{
    extern __shared__ float smf[];
    int tid = threadIdx.x;
    int lane = tid & 31, wid = tid >> 5;
    int wm = (wid & 3) * 32;
    int wn = (wid >> 2) * 64;
    int g = lane >> 2, t = lane & 3;

    unsigned smem_base = (unsigned)__cvta_generic_to_shared(smf);

    float c[2][8][4];
#pragma unroll
    for (int mi = 0; mi < 2; mi++)
#pragma unroll
        for (int nj = 0; nj < 8; nj++)
#pragma unroll
            for (int r = 0; r < 4; r++) c[mi][nj][r] = 0.f;

    const int KT = K / BKK;

    auto load_stage = [&](int s, int kt) {
        int k0 = kt * BKK;
        unsigned sa = smem_base + (unsigned)(s * GEMM_STAGE) * 4u;
        unsigned sb = sa + (unsigned)GEMM_ASZ * 4u;
#pragma unroll
        for (int i = 0; i < 4; i++) {
            int idx = tid + 256 * i;
            int row = idx >> 3;
            int kc  = (idx & 7) * 4;
            cp_async16(sa + (unsigned)(row * SAST + kc) * 4u,
                       &A[(size_t)(bm + row) * K + k0 + kc]);
            cp_async16(sb + (unsigned)(row * SAST + kc) * 4u,
                       &B[(size_t)(bn + row) * K + k0 + kc]);
        }
        cp_commit();
    };

    load_stage(0, 0);

    for (int kt = 0; kt < KT; kt++) {
        if (kt + 1 < KT) { load_stage((kt + 1) & 1, kt + 1); cp_wait1(); }
        else             { cp_wait0(); }
        __syncthreads();

        const float* As = smf + (kt & 1) * GEMM_STAGE;
        const float* Bs = As + GEMM_ASZ;

#pragma unroll
        for (int ks = 0; ks < 4; ks++) {
            int k0 = ks * 8;
            unsigned a[2][4], b[8][2];
#pragma unroll
            for (int mi = 0; mi < 2; mi++) {
                int r = wm + mi * 16;
                a[mi][0] = __float_as_uint(As[(r + g    ) * SAST + k0 + t    ]);
                a[mi][1] = __float_as_uint(As[(r + g + 8) * SAST + k0 + t    ]);
                a[mi][2] = __float_as_uint(As[(r + g    ) * SAST + k0 + t + 4]);
                a[mi][3] = __float_as_uint(As[(r + g + 8) * SAST + k0 + t + 4]);
            }
#pragma unroll
            for (int nj = 0; nj < 8; nj++) {
                int cb = wn + nj * 8;
                b[nj][0] = __float_as_uint(Bs[(cb + g) * SAST + k0 + t    ]);
                b[nj][1] = __float_as_uint(Bs[(cb + g) * SAST + k0 + t + 4]);
            }
#pragma unroll
            for (int mi = 0; mi < 2; mi++)
#pragma unroll
                for (int nj = 0; nj < 8; nj++)
                    mma_tf32(c[mi][nj], a[mi], b[nj]);
        }
        __syncthreads();
    }

#pragma unroll
    for (int mi = 0; mi < 2; mi++) {
#pragma unroll
        for (int nj = 0; nj < 8; nj++) {
            int row0 = bm + wm + mi * 16 + g;
            int col  = bn + wn + nj * 8 + 2 * t;
            float v0 = c[mi][nj][0], v1 = c[mi][nj][1];
            float v2 = c[mi][nj][2], v3 = c[mi][nj][3];
            if (round_out) {
                v0 = __uint_as_float(f2tf(v0)); v1 = __uint_as_float(f2tf(v1));
                v2 = __uint_as_float(f2tf(v2)); v3 = __uint_as_float(f2tf(v3));
            }
            *(float2*)&C[(size_t)row0 * N + col]       = make_float2(v0, v1);
            *(float2*)&C[(size_t)(row0 + 8) * N + col] = make_float2(v2, v3);
        }
    }
}

__global__ __launch_bounds__(256, 2) void gemm_tc_kernel(
    const float* __restrict__ A, const float* __restrict__ B,
    float* __restrict__ C, int M, int N, int K)
{
    gemm_tc(A, B, C, M, N, K, blockIdx.y * BM, blockIdx.x * BN, 0);
}

__global__ __launch_bounds__(256, 2) void gemm_tc_kv_kernel(
    const float* __restrict__ A,
    const float* __restrict__ B0, const float* __restrict__ B1,
    float* __restrict__ C0, float* __restrict__ C1, int M, int N, int K)
{
    const float* B = blockIdx.z ? B1 : B0;
    float* C = blockIdx.z ? C1 : C0;
    // round V output (z==1) to tf32 for the FA tensor-core PV mma
    gemm_tc(A, B, C, M, N, K, blockIdx.y * BM, blockIdx.x * BN, blockIdx.z);
}

// ---------------------------------------------------------------------------
// In-place RoPE; applies `scale` and rounds output to tf32 (FA mma operands).
// ---------------------------------------------------------------------------
__global__ void rope_kernel(float* __restrict__ u,
                            const float* __restrict__ cs,
                            const float* __restrict__ sn,
                            int heads, float scale)
{
    int idx = blockIdx.x * blockDim.x + threadIdx.x;
    int i = idx & 63;
    int h = (idx >> 6) % heads;
    int t = idx / (64 * heads);
    if (t >= TT) return;
    float c = cs[t * HD + i];
    float s = sn[t * HD + i];
    float* p = u + ((size_t)t * heads + h) * HD;
    float u1 = p[i], u2 = p[i + 64];
    p[i]      = __uint_as_float(f2tf((u1 * c - u2 * s) * scale));
    p[i + 64] = __uint_as_float(f2tf((u2 * c + u1 * s) * scale));
}

// ---------------------------------------------------------------------------
// Tensor-core flash attention (tf32). BQ=64, BKV=64, 128 threads (4 warps).
// Warp w owns q rows [w*16, w*16+16). S/O accumulators in registers.
// K/V tiles cp.async double-buffered. P never touches smem (shuffle transpose).
// smem: Qs[64][132] + 2 stages of (Ks[64][132] + Vs[64][136]).
// ---------------------------------------------------------------------------
#define FA_QST 132
#define FA_VST 136
#define FA_QSZ (64*FA_QST)               // 8448 floats
#define FA_KVSZ (64*FA_QST + 64*FA_VST)  // 17152 floats per stage
#define FA_SMEM ((FA_QSZ + 2*FA_KVSZ)*4) // 171008 bytes

__global__ __launch_bounds__(128, 1) void fa_tc_kernel(float* __restrict__ att)
{
    extern __shared__ float smf[];
    int tid = threadIdx.x;
    int lane = tid & 31, wid = tid >> 5;
    int g = lane >> 2, t = lane & 3;
    int w16 = wid * 16;

    int qb = gridDim.x - 1 - blockIdx.x;   // heavy blocks first
    int h  = blockIdx.y;
    int g0 = h / REP;

    unsigned smem_base = (unsigned)__cvta_generic_to_shared(smf);
    float* Qs = smf;

    // Load Q tile (pre-rounded tf32 values)
#pragma unroll
    for (int i = 0; i < 16; i++) {
        int idx = tid + 128 * i;       // 0..2047
        int r = idx >> 5;
        int c4 = (idx & 31) * 4;
        *(float4*)&Qs[r*FA_QST + c4] =
            *(const float4*)&g_q[(size_t)(qb*64 + r) * NQ + h*HD + c4];
    }

    auto load_kv = [&](int kb, int s) {
        const float* Kg = &g_k[(size_t)(kb*64) * NKV + g0*HD];
        const float* Vg = &g_v[(size_t)(kb*64) * NKV + g0*HD];
        unsigned kbase = smem_base + (unsigned)(FA_QSZ + s*FA_KVSZ) * 4u;
        unsigned vbase = kbase + (unsigned)(64*FA_QST) * 4u;
#pragma unroll
        for (int i = 0; i < 16; i++) {
            int idx = tid + 128 * i;
            int r = idx >> 5;
            int c4 = (idx & 31) * 4;
            cp_async16(kbase + (unsigned)(r*FA_QST + c4) * 4u,
                       Kg + (size_t)r*NKV + c4);
            cp_async16(vbase + (unsigned)(r*FA_VST + c4) * 4u,
                       Vg + (size_t)r*NKV + c4);
        }
        cp_commit();
    };

    float o[16][4];
#pragma unroll
    for (int nj = 0; nj < 16; nj++)
#pragma unroll
        for (int r = 0; r < 4; r++) o[nj][r] = 0.f;
    float m0 = -1e30f, m1 = -1e30f, l0 = 0.f, l1 = 0.f;

    load_kv(0, 0);

    for (int kb = 0; kb <= qb; kb++) {
        if (kb < qb) { load_kv(kb + 1, (kb + 1) & 1); cp_wait1(); }
        else         { cp_wait0(); }
        __syncthreads();

        const float* Ks = smf + FA_QSZ + (kb & 1) * FA_KVSZ;
        const float* Vs = Ks + 64*FA_QST;

        // ---- S = Q K^T : warp computes 16x64 into s[8][4] ----
        float s[8][4];
#pragma unroll
        for (int nj = 0; nj < 8; nj++)
#pragma unroll
            for (int r = 0; r < 4; r++) s[nj][r] = 0.f;

#pragma unroll
        for (int ks = 0; ks < 16; ks++) {
            int k0 = ks * 8;
            unsigned a[4];
            a[0] = __float_as_uint(Qs[(w16 + g    )*FA_QST + k0 + t    ]);
            a[1] = __float_as_uint(Qs[(w16 + g + 8)*FA_QST + k0 + t    ]);
            a[2] = __float_as_uint(Qs[(w16 + g    )*FA_QST + k0 + t + 4]);
            a[3] = __float_as_uint(Qs[(w16 + g + 8)*FA_QST + k0 + t + 4]);
#pragma unroll
            for (int nj = 0; nj < 8; nj++) {
                unsigned b[2];
                b[0] = __float_as_uint(Ks[(nj*8 + g)*FA_QST + k0 + t    ]);
                b[1] = __float_as_uint(Ks[(nj*8 + g)*FA_QST + k0 + t + 4]);
                mma_tf32(s[nj], a, b);
            }
        }

        // ---- causal mask on the diagonal block ----
        if (kb == qb) {
            int r0 = w16 + g, r1 = r0 + 8;
#pragma unroll
            for (int nj = 0; nj < 8; nj++) {
                int c0 = nj*8 + 2*t, c1 = c0 + 1;
                if (c0 > r0) s[nj][0] = -1e30f;
                if (c1 > r0) s[nj][1] = -1e30f;
                if (c0 > r1) s[nj][2] = -1e30f;
                if (c1 > r1) s[nj][3] = -1e30f;
            }
        }

        // ---- online softmax (register, quad shuffle reduction) ----
        float mx0 = -1e30f, mx1 = -1e30f;
#pragma unroll
        for (int nj = 0; nj < 8; nj++) {
            mx0 = fmaxf(mx0, fmaxf(s[nj][0], s[nj][1]));
            mx1 = fmaxf(mx1, fmaxf(s[nj][2], s[nj][3]));
        }
        mx0 = fmaxf(mx0, __shfl_xor_sync(0xffffffffu, mx0, 1));
        mx0 = fmaxf(mx0, __shfl_xor_sync(0xffffffffu, mx0, 2));
        mx1 = fmaxf(mx1, __shfl_xor_sync(0xffffffffu, mx1, 1));
        mx1 = fmaxf(mx1, __shfl_xor_sync(0xffffffffu, mx1, 2));
        float mn0 = fmaxf(m0, mx0), mn1 = fmaxf(m1, mx1);
        float al0 = __expf(m0 - mn0), al1 = __expf(m1 - mn1);
        m0 = mn0; m1 = mn1;

        float rs0 = 0.f, rs1 = 0.f;
#pragma unroll
        for (int nj = 0; nj < 8; nj++) {
            s[nj][0] = __expf(s[nj][0] - mn0);
            s[nj][1] = __expf(s[nj][1] - mn0);
            s[nj][2] = __expf(s[nj][2] - mn1);
            s[nj][3] = __expf(s[nj][3] - mn1);
            rs0 += s[nj][0] + s[nj][1];
            rs1 += s[nj][2] + s[nj][3];
        }
        rs0 += __shfl_xor_sync(0xffffffffu, rs0, 1);
        rs0 += __shfl_xor_sync(0xffffffffu, rs0, 2);
        rs1 += __shfl_xor_sync(0xffffffffu, rs1, 1);
        rs1 += __shfl_xor_sync(0xffffffffu, rs1, 2);
        l0 = l0 * al0 + rs0;
        l1 = l1 * al1 + rs1;

#pragma unroll
        for (int nj = 0; nj < 16; nj++) {
            o[nj][0] *= al0; o[nj][1] *= al0;
            o[nj][2] *= al1; o[nj][3] *= al1;
        }

        // ---- O += P @ V : shuffle-transpose C-frag -> A-frag per k-tile ----
        int src0 = (lane & ~3) + (t >> 1);
        int src1 = src0 + 2;
#pragma unroll
        for (int kt = 0; kt < 8; kt++) {
            float p00 = __shfl_sync(0xffffffffu, s[kt][0], src0);
            float p01 = __shfl_sync(0xffffffffu, s[kt][1], src0);
            float p20 = __shfl_sync(0xffffffffu, s[kt][2], src0);
            float p21 = __shfl_sync(0xffffffffu, s[kt][3], src0);
            float q00 = __shfl_sync(0xffffffffu, s[kt][0], src1);
            float q01 = __shfl_sync(0xffffffffu, s[kt][1], src1);
            float q20 = __shfl_sync(0xffffffffu, s[kt][2], src1);
            float q21 = __shfl_sync(0xffffffffu, s[kt][3], src1);
            unsigned a[4];
            a[0] = f2tf((t & 1) ? p01 : p00);
            a[1] = f2tf((t & 1) ? p21 : p20);
            a[2] = f2tf((t & 1) ? q01 : q00);
            a[3] = f2tf((t & 1) ? q21 : q20);
#pragma unroll
            for (int nj = 0; nj < 16; nj++) {
                unsigned b[2];
                b[0] = __float_as_uint(Vs[(kt*8 + t    )*FA_VST + nj*8 + g]);
                b[1] = __float_as_uint(Vs[(kt*8 + t + 4)*FA_VST + nj*8 + g]);
                mma_tf32(o[nj], a, b);
            }
        }
        __syncthreads();
    }

    // ---- epilogue: normalize, round to tf32, write ----
    float il0 = 1.0f / l0, il1 = 1.0f / l1;
#pragma unroll
    for (int nj = 0; nj < 16; nj++) {
        int row0 = qb*64 + w16 + g;
        int col  = h*HD + nj*8 + 2*t;
        float2 v0 = make_float2(__uint_as_float(f2tf(o[nj][0]*il0)),
                                __uint_as_float(f2tf(o[nj][1]*il0)));
        float2 v1 = make_float2(__uint_as_float(f2tf(o[nj][2]*il1)),
                                __uint_as_float(f2tf(o[nj][3]*il1)));
        *(float2*)&att[(size_t)row0 * NQ + col]       = v0;
        *(float2*)&att[(size_t)(row0 + 8) * NQ + col] = v1;
    }
}

// ---------------------------------------------------------------------------
extern "C" void kernel_launch(void* const* d_in, const int* in_sizes, int n_in,
                              void* d_out, int out_size)
{
    const float* x  = (const float*)d_in[0];
    const float* wq = (const float*)d_in[1];
    const float* wk = (const float*)d_in[2];
    const float* wv = (const float*)d_in[3];
    const float* wo = (const float*)d_in[4];
    const float* cs = (const float*)d_in[5];
    const float* sn = (const float*)d_in[6];
    float* out = (float*)d_out;

    float *q, *k, *v, *att, *xr, *wqr, *wkr, *wvr, *wor;
    cudaGetSymbolAddress((void**)&q,   g_q);
    cudaGetSymbolAddress((void**)&k,   g_k);
    cudaGetSymbolAddress((void**)&v,   g_v);
    cudaGetSymbolAddress((void**)&att, g_att);
    cudaGetSymbolAddress((void**)&xr,  g_xr);
    cudaGetSymbolAddress((void**)&wqr, g_wqr);
    cudaGetSymbolAddress((void**)&wkr, g_wkr);
    cudaGetSymbolAddress((void**)&wvr, g_wvr);
    cudaGetSymbolAddress((void**)&wor, g_wor);

    static bool attr_set = false;
    if (!attr_set) {
        cudaFuncSetAttribute(gemm_tc_kernel,
            cudaFuncAttributeMaxDynamicSharedMemorySize, GEMM_SMEM);
        cudaFuncSetAttribute(gemm_tc_kv_kernel,
            cudaFuncAttributeMaxDynamicSharedMemorySize, GEMM_SMEM);
        cudaFuncSetAttribute(fa_tc_kernel,
            cudaFuncAttributeMaxDynamicSharedMemorySize, FA_SMEM);
        attr_set = true;
    }

    // Pre-round GEMM inputs to tf32
    round_tf32_kernel<<<(TT*DIMD/4 + 255)/256,  256>>>(x,  xr,  TT*DIMD/4);
    round_tf32_kernel<<<(NQ*DIMD/4 + 255)/256,  256>>>(wq, wqr, NQ*DIMD/4);
    round_tf32_kernel<<<(NKV*DIMD/4 + 255)/256, 256>>>(wk, wkr, NKV*DIMD/4);
    round_tf32_kernel<<<(NKV*DIMD/4 + 255)/256, 256>>>(wv, wvr, NKV*DIMD/4);
    round_tf32_kernel<<<(DIMD*NQ/4 + 255)/256,  256>>>(wo, wor, DIMD*NQ/4);

    // QKV projections on tensor cores (V output rounded to tf32)
    gemm_tc_kernel<<<dim3(NQ/BN, TT/BM), 256, GEMM_SMEM>>>(
        xr, wqr, q, TT, NQ, DIMD);
    gemm_tc_kv_kernel<<<dim3(NKV/BN, TT/BM, 2), 256, GEMM_SMEM>>>(
        xr, wkr, wvr, k, v, TT, NKV, DIMD);

    // RoPE (rounds Q/K to tf32; Q also gets 1/sqrt(HD) folded in)
    const float scale = 0.08838834764831845f;  // 128^-0.5
    rope_kernel<<<(TT*NH*64)/256,   256>>>(q, cs, sn, NH,   scale);
    rope_kernel<<<(TT*NKVH*64)/256, 256>>>(k, cs, sn, NKVH, 1.0f);

    // Tensor-core flash attention
    fa_tc_kernel<<<dim3(TT/64, NH), 128, FA_SMEM>>>(att);

    // Output projection on tensor cores
    gemm_tc_kernel<<<dim3(DIMD/BN, TT/BM), 256, GEMM_SMEM>>>(
        att, wor, out, TT, DIMD, NQ);
}

// round 4
// speedup vs baseline: 4.8226x; 1.2093x over previous
#include <cuda_runtime.h>
#include <math.h>

#define TT 2048
#define DIMD 2048
#define NH 16
#define NKVH 4
#define HD 128
#define NQ (NH*HD)     // 2048
#define NKV (NKVH*HD)  // 512
#define REP (NH/NKVH)  // 4

// Scratch (device globals; allocation in kernel_launch is forbidden)
__device__ float g_q[TT*NQ];
__device__ float g_k[TT*NKV];
__device__ float g_v[TT*NKV];
__device__ float g_att[TT*NQ];
// tf32-rounded copies of GEMM inputs
__device__ float g_xr [TT*DIMD];
__device__ float g_wqr[NQ*DIMD];
__device__ float g_wkr[NKV*DIMD];
__device__ float g_wvr[NKV*DIMD];
__device__ float g_wor[DIMD*NQ];

// ---------------------------------------------------------------------------
// helpers
// ---------------------------------------------------------------------------
__device__ __forceinline__ unsigned f2tf(float f) {
    unsigned u; asm("cvt.rna.tf32.f32 %0, %1;" : "=r"(u) : "f"(f)); return u;
}

__global__ void round_tf32_kernel(const float* __restrict__ in,
                                  float* __restrict__ out, int n4)
{
    int i = blockIdx.x * blockDim.x + threadIdx.x;
    if (i >= n4) return;
    float4 v = ((const float4*)in)[i];
    uint4 o;
    o.x = f2tf(v.x); o.y = f2tf(v.y); o.z = f2tf(v.z); o.w = f2tf(v.w);
    ((uint4*)out)[i] = o;
}

__device__ __forceinline__ void cp_async16(unsigned saddr, const void* g) {
    asm volatile("cp.async.cg.shared.global [%0], [%1], 16;\n"
                 :: "r"(saddr), "l"(g));
}
__device__ __forceinline__ void cp_commit() {
    asm volatile("cp.async.commit_group;\n");
}
__device__ __forceinline__ void cp_wait0() {
    asm volatile("cp.async.wait_group 0;\n");
}
__device__ __forceinline__ void cp_wait1() {
    asm volatile("cp.async.wait_group 1;\n");
}

__device__ __forceinline__ void mma_tf32(float c[4], const uint4& a,
                                         unsigned b0, unsigned b1) {
    asm volatile(
        "mma.sync.aligned.m16n8k8.row.col.f32.tf32.tf32.f32 "
        "{%0,%1,%2,%3}, {%4,%5,%6,%7}, {%8,%9}, {%0,%1,%2,%3};\n"
        : "+f"(c[0]), "+f"(c[1]), "+f"(c[2]), "+f"(c[3])
        : "r"(a.x), "r"(a.y), "r"(a.z), "r"(a.w), "r"(b0), "r"(b1));
}

// ldmatrix x4: four 8x8 b16 (= 8x4 fp32) tiles; lane supplies its row address.
__device__ __forceinline__ void ldsm_x4(uint4& d, unsigned addr) {
    asm volatile(
        "ldmatrix.sync.aligned.m8n8.x4.shared.b16 {%0,%1,%2,%3}, [%4];\n"
        : "=r"(d.x), "=r"(d.y), "=r"(d.z), "=r"(d.w) : "r"(addr));
}

// ---------------------------------------------------------------------------
// Tensor-core tf32 GEMM: C[M,N] = A[M,K] * B[N,K]^T, A/B pre-rounded to tf32.
// 128x128 tile, BK=32, 256 threads (8 warps, 4x2), warp tile 32x64.
// Fragments loaded via ldmatrix (conflict-free with stride 36).
// ---------------------------------------------------------------------------
#define BM 128
#define BN 128
#define BKK 32
#define SAST 36
#define GEMM_ASZ (BM*SAST)
#define GEMM_STAGE (2*GEMM_ASZ)
#define GEMM_SMEM (2*GEMM_STAGE*4)

__device__ __forceinline__ void gemm_tc(
    const float* __restrict__ A, const float* __restrict__ B,
    float* __restrict__ C, int N, int K, int bm, int bn, int round_out)
{
    extern __shared__ float smf[];
    int tid = threadIdx.x;
    int lane = tid & 31, wid = tid >> 5;
    int wm = (wid & 3) * 32;
    int wn = (wid >> 2) * 64;
    int g = lane >> 2, t = lane & 3;

    // ldmatrix lane->row mapping
    int lrow = lane & 7;
    int am   = lane >> 3;            // matrix index 0..3
    int a_row  = wm + ((am & 1) << 3) + lrow;
    int a_col4 = (am >> 1) << 2;
    int b_row  = wn + ((am >> 1) << 3) + lrow;
    int b_col4 = (am & 1) << 2;

    unsigned smem_base = (unsigned)__cvta_generic_to_shared(smf);

    float c[2][8][4];
#pragma unroll
    for (int mi = 0; mi < 2; mi++)
#pragma unroll
        for (int nj = 0; nj < 8; nj++)
#pragma unroll
            for (int r = 0; r < 4; r++) c[mi][nj][r] = 0.f;

    const int KT = K / BKK;

    auto load_stage = [&](int s, int kt) {
        int k0 = kt * BKK;
        unsigned sa = smem_base + (unsigned)(s * GEMM_STAGE) * 4u;
        unsigned sb = sa + (unsigned)GEMM_ASZ * 4u;
#pragma unroll
        for (int i = 0; i < 4; i++) {
            int idx = tid + 256 * i;
            int row = idx >> 3;
            int kc  = (idx & 7) * 4;
            cp_async16(sa + (unsigned)(row * SAST + kc) * 4u,
                       &A[(size_t)(bm + row) * K + k0 + kc]);
            cp_async16(sb + (unsigned)(row * SAST + kc) * 4u,
                       &B[(size_t)(bn + row) * K + k0 + kc]);
        }
        cp_commit();
    };

    load_stage(0, 0);

    for (int kt = 0; kt < KT; kt++) {
        if (kt + 1 < KT) { load_stage((kt + 1) & 1, kt + 1); cp_wait1(); }
        else             { cp_wait0(); }
        __syncthreads();

        unsigned sA = smem_base + (unsigned)((kt & 1) * GEMM_STAGE) * 4u;
        unsigned sB = sA + (unsigned)GEMM_ASZ * 4u;

#pragma unroll
        for (int ks = 0; ks < 4; ks++) {
            int k0 = ks * 8;
            uint4 a[2], bp[4];
#pragma unroll
            for (int mi = 0; mi < 2; mi++)
                ldsm_x4(a[mi], sA + (unsigned)((a_row + mi*16) * SAST
                                               + k0 + a_col4) * 4u);
#pragma unroll
            for (int p = 0; p < 4; p++)
                ldsm_x4(bp[p], sB + (unsigned)((b_row + p*16) * SAST
                                               + k0 + b_col4) * 4u);
#pragma unroll
            for (int mi = 0; mi < 2; mi++)
#pragma unroll
                for (int p = 0; p < 4; p++) {
                    mma_tf32(c[mi][2*p  ], a[mi], bp[p].x, bp[p].y);
                    mma_tf32(c[mi][2*p+1], a[mi], bp[p].z, bp[p].w);
                }
        }
        __syncthreads();
    }

#pragma unroll
    for (int mi = 0; mi < 2; mi++) {
#pragma unroll
        for (int nj = 0; nj < 8; nj++) {
            int row0 = bm + wm + mi * 16 + g;
            int col  = bn + wn + nj * 8 + 2 * t;
            float v0 = c[mi][nj][0], v1 = c[mi][nj][1];
            float v2 = c[mi][nj][2], v3 = c[mi][nj][3];
            if (round_out) {
                v0 = __uint_as_float(f2tf(v0)); v1 = __uint_as_float(f2tf(v1));
                v2 = __uint_as_float(f2tf(v2)); v3 = __uint_as_float(f2tf(v3));
            }
            *(float2*)&C[(size_t)row0 * N + col]       = make_float2(v0, v1);
            *(float2*)&C[(size_t)(row0 + 8) * N + col] = make_float2(v2, v3);
        }
    }
}

// Fused Q/K/V projections: grid.x = 16 (Q) + 4 (K) + 4 (V), grid.y = 16.
__global__ __launch_bounds__(256, 2) void qkv_gemm_kernel(
    const float* __restrict__ A,
    const float* __restrict__ Bq, const float* __restrict__ Bk,
    const float* __restrict__ Bv,
    float* __restrict__ Cq, float* __restrict__ Ck, float* __restrict__ Cv)
{
    int bx = blockIdx.x, bm = blockIdx.y * BM;
    if (bx < 16)      gemm_tc(A, Bq, Cq, NQ,  DIMD, bm, bx * BN, 0);
    else if (bx < 20) gemm_tc(A, Bk, Ck, NKV, DIMD, bm, (bx-16) * BN, 0);
    else              gemm_tc(A, Bv, Cv, NKV, DIMD, bm, (bx-20) * BN, 1);
}

__global__ __launch_bounds__(256, 2) void gemm_tc_kernel(
    const float* __restrict__ A, const float* __restrict__ B,
    float* __restrict__ C, int N, int K)
{
    gemm_tc(A, B, C, N, K, blockIdx.y * BM, blockIdx.x * BN, 0);
}

// ---------------------------------------------------------------------------
// In-place RoPE; applies `scale` and rounds output to tf32 (FA mma operands).
// ---------------------------------------------------------------------------
__global__ void rope_kernel(float* __restrict__ u,
                            const float* __restrict__ cs,
                            const float* __restrict__ sn,
                            int heads, float scale)
{
    int idx = blockIdx.x * blockDim.x + threadIdx.x;
    int i = idx & 63;
    int h = (idx >> 6) % heads;
    int t = idx / (64 * heads);
    if (t >= TT) return;
    float c = cs[t * HD + i];
    float s = sn[t * HD + i];
    float* p = u + ((size_t)t * heads + h) * HD;
    float u1 = p[i], u2 = p[i + 64];
    p[i]      = __uint_as_float(f2tf((u1 * c - u2 * s) * scale));
    p[i + 64] = __uint_as_float(f2tf((u2 * c + u1 * s) * scale));
}

// ---------------------------------------------------------------------------
// Tensor-core flash attention (tf32). BQ=128, BKV=64, 256 threads (8 warps).
// Warp w owns q rows [w*16, w*16+16). Q/K frags via ldmatrix, V scalar.
// K/V tiles cp.async double-buffered. P stays in registers (shuffle transpose).
// smem: Qs[128][132] + 2 stages of (Ks[64][132] + Vs[64][136]) = 204800 B.
// ---------------------------------------------------------------------------
#define FAQ 128
#define FA_QST 132
#define FA_VST 136
#define FA_QSZ (FAQ*FA_QST)              // 16896 floats
#define FA_KSZ (64*FA_QST)               // 8448
#define FA_KVSZ (FA_KSZ + 64*FA_VST)     // 17152 floats per stage
#define FA_SMEM ((FA_QSZ + 2*FA_KVSZ)*4) // 204800 bytes

__global__ __launch_bounds__(256, 1) void fa_tc_kernel(float* __restrict__ att)
{
    extern __shared__ float smf[];
    int tid = threadIdx.x;
    int lane = tid & 31, wid = tid >> 5;
    int g = lane >> 2, t = lane & 3;
    int w16 = wid * 16;

    int lrow = lane & 7;
    int am   = lane >> 3;
    int a_row  = w16 + ((am & 1) << 3) + lrow;   // Q frag rows
    int a_col4 = (am >> 1) << 2;
    int b_row  = ((am >> 1) << 3) + lrow;        // K frag rows (+p*16)
    int b_col4 = (am & 1) << 2;

    int h  = blockIdx.x;
    int qb = gridDim.y - 1 - blockIdx.y;   // heavy blocks first
    int g0 = h / REP;

    unsigned smem_base = (unsigned)__cvta_generic_to_shared(smf);
    float* Qs = smf;

    // Load Q tile (pre-rounded tf32)
#pragma unroll
    for (int i = 0; i < 16; i++) {
        int idx = tid + 256 * i;        // 0..4095
        int r = idx >> 5;
        int c4 = (idx & 31) * 4;
        *(float4*)&Qs[r*FA_QST + c4] =
            *(const float4*)&g_q[(size_t)(qb*FAQ + r) * NQ + h*HD + c4];
    }

    auto load_kv = [&](int kb, int s) {
        const float* Kg = &g_k[(size_t)(kb*64) * NKV + g0*HD];
        const float* Vg = &g_v[(size_t)(kb*64) * NKV + g0*HD];
        unsigned kbase = smem_base + (unsigned)(FA_QSZ + s*FA_KVSZ) * 4u;
        unsigned vbase = kbase + (unsigned)FA_KSZ * 4u;
#pragma unroll
        for (int i = 0; i < 8; i++) {
            int idx = tid + 256 * i;   // 0..2047
            int r = idx >> 5;
            int c4 = (idx & 31) * 4;
            cp_async16(kbase + (unsigned)(r*FA_QST + c4) * 4u,
                       Kg + (size_t)r*NKV + c4);
            cp_async16(vbase + (unsigned)(r*FA_VST + c4) * 4u,
                       Vg + (size_t)r*NKV + c4);
        }
        cp_commit();
    };

    float o[16][4];
#pragma unroll
    for (int nj = 0; nj < 16; nj++)
#pragma unroll
        for (int r = 0; r < 4; r++) o[nj][r] = 0.f;
    float m0 = -1e30f, m1 = -1e30f, l0 = 0.f, l1 = 0.f;

    const int kb_max = 2*qb + 1;
    load_kv(0, 0);

    for (int kb = 0; kb <= kb_max; kb++) {
        if (kb < kb_max) { load_kv(kb + 1, (kb + 1) & 1); cp_wait1(); }
        else             { cp_wait0(); }
        __syncthreads();

        unsigned sK = smem_base + (unsigned)(FA_QSZ + (kb & 1)*FA_KVSZ) * 4u;
        const float* Vs = smf + FA_QSZ + (kb & 1)*FA_KVSZ + FA_KSZ;

        // ---- S = Q K^T : warp computes 16x64 into s[8][4] ----
        float s[8][4];
#pragma unroll
        for (int nj = 0; nj < 8; nj++)
#pragma unroll
            for (int r = 0; r < 4; r++) s[nj][r] = 0.f;

#pragma unroll
        for (int ks = 0; ks < 16; ks++) {
            int k0 = ks * 8;
            uint4 a, bp[4];
            ldsm_x4(a, smem_base + (unsigned)(a_row*FA_QST + k0 + a_col4)*4u);
#pragma unroll
            for (int p = 0; p < 4; p++)
                ldsm_x4(bp[p], sK + (unsigned)((b_row + p*16)*FA_QST
                                               + k0 + b_col4)*4u);
#pragma unroll
            for (int p = 0; p < 4; p++) {
                mma_tf32(s[2*p  ], a, bp[p].x, bp[p].y);
                mma_tf32(s[2*p+1], a, bp[p].z, bp[p].w);
            }
        }

        // ---- causal mask (only near-diagonal blocks) ----
        if (kb >= 2*qb) {
            int r0 = qb*FAQ + w16 + g, r1 = r0 + 8;
            int cb0 = kb*64 + 2*t;
#pragma unroll
            for (int nj = 0; nj < 8; nj++) {
                int c0 = cb0 + nj*8, c1 = c0 + 1;
                if (c0 > r0) s[nj][0] = -1e30f;
                if (c1 > r0) s[nj][1] = -1e30f;
                if (c0 > r1) s[nj][2] = -1e30f;
                if (c1 > r1) s[nj][3] = -1e30f;
            }
        }

        // ---- online softmax (register, quad shuffle reduction) ----
        float mx0 = -1e30f, mx1 = -1e30f;
#pragma unroll
        for (int nj = 0; nj < 8; nj++) {
            mx0 = fmaxf(mx0, fmaxf(s[nj][0], s[nj][1]));
            mx1 = fmaxf(mx1, fmaxf(s[nj][2], s[nj][3]));
        }
        mx0 = fmaxf(mx0, __shfl_xor_sync(0xffffffffu, mx0, 1));
        mx0 = fmaxf(mx0, __shfl_xor_sync(0xffffffffu, mx0, 2));
        mx1 = fmaxf(mx1, __shfl_xor_sync(0xffffffffu, mx1, 1));
        mx1 = fmaxf(mx1, __shfl_xor_sync(0xffffffffu, mx1, 2));
        float mn0 = fmaxf(m0, mx0), mn1 = fmaxf(m1, mx1);
        float al0 = __expf(m0 - mn0), al1 = __expf(m1 - mn1);
        m0 = mn0; m1 = mn1;

        float rs0 = 0.f, rs1 = 0.f;
#pragma unroll
        for (int nj = 0; nj < 8; nj++) {
            s[nj][0] = __expf(s[nj][0] - mn0);
            s[nj][1] = __expf(s[nj][1] - mn0);
            s[nj][2] = __expf(s[nj][2] - mn1);
            s[nj][3] = __expf(s[nj][3] - mn1);
            rs0 += s[nj][0] + s[nj][1];
            rs1 += s[nj][2] + s[nj][3];
        }
        rs0 += __shfl_xor_sync(0xffffffffu, rs0, 1);
        rs0 += __shfl_xor_sync(0xffffffffu, rs0, 2);
        rs1 += __shfl_xor_sync(0xffffffffu, rs1, 1);
        rs1 += __shfl_xor_sync(0xffffffffu, rs1, 2);
        l0 = l0 * al0 + rs0;
        l1 = l1 * al1 + rs1;

#pragma unroll
        for (int nj = 0; nj < 16; nj++) {
            o[nj][0] *= al0; o[nj][1] *= al0;
            o[nj][2] *= al1; o[nj][3] *= al1;
        }

        // ---- O += P @ V : shuffle-transpose C-frag -> A-frag per k-tile ----
        int src0 = (lane & ~3) + (t >> 1);
        int src1 = src0 + 2;
#pragma unroll
        for (int kt = 0; kt < 8; kt++) {
            float p00 = __shfl_sync(0xffffffffu, s[kt][0], src0);
            float p01 = __shfl_sync(0xffffffffu, s[kt][1], src0);
            float p20 = __shfl_sync(0xffffffffu, s[kt][2], src0);
            float p21 = __shfl_sync(0xffffffffu, s[kt][3], src0);
            float q00 = __shfl_sync(0xffffffffu, s[kt][0], src1);
            float q01 = __shfl_sync(0xffffffffu, s[kt][1], src1);
            float q20 = __shfl_sync(0xffffffffu, s[kt][2], src1);
            float q21 = __shfl_sync(0xffffffffu, s[kt][3], src1);
            uint4 a;
            a.x = f2tf((t & 1) ? p01 : p00);
            a.y = f2tf((t & 1) ? p21 : p20);
            a.z = f2tf((t & 1) ? q01 : q00);
            a.w = f2tf((t & 1) ? q21 : q20);
#pragma unroll
            for (int nj = 0; nj < 16; nj++) {
                unsigned b0 = __float_as_uint(Vs[(kt*8 + t    )*FA_VST + nj*8 + g]);
                unsigned b1 = __float_as_uint(Vs[(kt*8 + t + 4)*FA_VST + nj*8 + g]);
                mma_tf32(o[nj], a, b0, b1);
            }
        }
        __syncthreads();
    }

    // ---- epilogue: normalize, round to tf32, write ----
    float il0 = 1.0f / l0, il1 = 1.0f / l1;
#pragma unroll
    for (int nj = 0; nj < 16; nj++) {
        int row0 = qb*FAQ + w16 + g;
        int col  = h*HD + nj*8 + 2*t;
        float2 v0 = make_float2(__uint_as_float(f2tf(o[nj][0]*il0)),
                                __uint_as_float(f2tf(o[nj][1]*il0)));
        float2 v1 = make_float2(__uint_as_float(f2tf(o[nj][2]*il1)),
                                __uint_as_float(f2tf(o[nj][3]*il1)));
        *(float2*)&att[(size_t)row0 * NQ + col]       = v0;
        *(float2*)&att[(size_t)(row0 + 8) * NQ + col] = v1;
    }
}

// ---------------------------------------------------------------------------
extern "C" void kernel_launch(void* const* d_in, const int* in_sizes, int n_in,
                              void* d_out, int out_size)
{
    const float* x  = (const float*)d_in[0];
    const float* wq = (const float*)d_in[1];
    const float* wk = (const float*)d_in[2];
    const float* wv = (const float*)d_in[3];
    const float* wo = (const float*)d_in[4];
    const float* cs = (const float*)d_in[5];
    const float* sn = (const float*)d_in[6];
    float* out = (float*)d_out;

    float *q, *k, *v, *att, *xr, *wqr, *wkr, *wvr, *wor;
    cudaGetSymbolAddress((void**)&q,   g_q);
    cudaGetSymbolAddress((void**)&k,   g_k);
    cudaGetSymbolAddress((void**)&v,   g_v);
    cudaGetSymbolAddress((void**)&att, g_att);
    cudaGetSymbolAddress((void**)&xr,  g_xr);
    cudaGetSymbolAddress((void**)&wqr, g_wqr);
    cudaGetSymbolAddress((void**)&wkr, g_wkr);
    cudaGetSymbolAddress((void**)&wvr, g_wvr);
    cudaGetSymbolAddress((void**)&wor, g_wor);

    static bool attr_set = false;
    if (!attr_set) {
        cudaFuncSetAttribute(qkv_gemm_kernel,
            cudaFuncAttributeMaxDynamicSharedMemorySize, GEMM_SMEM);
        cudaFuncSetAttribute(gemm_tc_kernel,
            cudaFuncAttributeMaxDynamicSharedMemorySize, GEMM_SMEM);
        cudaFuncSetAttribute(fa_tc_kernel,
            cudaFuncAttributeMaxDynamicSharedMemorySize, FA_SMEM);
        attr_set = true;
    }

    // Pre-round GEMM inputs to tf32
    round_tf32_kernel<<<(TT*DIMD/4 + 255)/256,  256>>>(x,  xr,  TT*DIMD/4);
    round_tf32_kernel<<<(NQ*DIMD/4 + 255)/256,  256>>>(wq, wqr, NQ*DIMD/4);
    round_tf32_kernel<<<(NKV*DIMD/4 + 255)/256, 256>>>(wk, wkr, NKV*DIMD/4);
    round_tf32_kernel<<<(NKV*DIMD/4 + 255)/256, 256>>>(wv, wvr, NKV*DIMD/4);
    round_tf32_kernel<<<(DIMD*NQ/4 + 255)/256,  256>>>(wo, wor, DIMD*NQ/4);

    // Fused QKV projection (V output rounded to tf32 for FA)
    qkv_gemm_kernel<<<dim3(24, TT/BM), 256, GEMM_SMEM>>>(
        xr, wqr, wkr, wvr, q, k, v);

    // RoPE (rounds Q/K to tf32; Q also gets 1/sqrt(HD) folded in)
    const float scale = 0.08838834764831845f;  // 128^-0.5
    rope_kernel<<<(TT*NH*64)/256,   256>>>(q, cs, sn, NH,   scale);
    rope_kernel<<<(TT*NKVH*64)/256, 256>>>(k, cs, sn, NKVH, 1.0f);

    // Tensor-core flash attention (BQ=128, heavy blocks first)
    fa_tc_kernel<<<dim3(NH, TT/FAQ), 256, FA_SMEM>>>(att);

    // Output projection on tensor cores
    gemm_tc_kernel<<<dim3(DIMD/BN, TT/BM), 256, GEMM_SMEM>>>(
        att, wor, out, NQ, NQ);
}